// round 1
// baseline (speedup 1.0000x reference)
#include <cuda_runtime.h>
#include <stdint.h>

// Compile-time constants for this problem instance:
//   B = 1048576, D = 3, L = 16, C = 2, H = 16, S = 1.0
//   res(l)  = 16 << l, side(l) = res+1
//   dense levels: l = 0,1,2  (side^3 <= hm, so % hm is identity)
//   hashed levels: l >= 3, hm = 524288 = 2^19  -> & 0x7FFFF
//   offsets: 0, 4920, 40864, 315496, then +524288 per level
//   table = concat(ext[524288,2], own[.,2]); split handled by pointer select.

#define HASH_SPLIT 524288u
#define P2 2654435761u
#define P3 805459861u

__global__ void __launch_bounds__(256)
grid_encode_kernel(const float* __restrict__ pts,
                   const float2* __restrict__ ext,
                   const float2* __restrict__ own,
                   float2* __restrict__ out)
{
    const unsigned gtid = blockIdx.x * 256u + threadIdx.x;
    const unsigned b = gtid >> 4;
    const unsigned l = gtid & 15u;

    // Load the point (broadcast within half-warp; L1/L2 friendly).
    const float px_in = pts[3u * b + 0u];
    const float py_in = pts[3u * b + 1u];
    const float pz_in = pts[3u * b + 2u];

    const unsigned res  = 16u << l;
    const float scale   = (float)(res - 1u);
    const unsigned side = res + 1u;

    // x01 = (x+1)/2 ; pos = x01*scale + 0.5
    const float posx = (px_in + 1.0f) * 0.5f * scale + 0.5f;
    const float posy = (py_in + 1.0f) * 0.5f * scale + 0.5f;
    const float posz = (pz_in + 1.0f) * 0.5f * scale + 0.5f;

    const float flx = floorf(posx);
    const float fly = floorf(posy);
    const float flz = floorf(posz);
    const float fx = posx - flx;
    const float fy = posy - fly;
    const float fz = posz - flz;
    const unsigned x0 = (unsigned)flx;
    const unsigned y0 = (unsigned)fly;
    const unsigned z0 = (unsigned)flz;

    const bool hashed = (l >= 3u);
    const unsigned off = hashed ? (315496u + (l - 3u) * 524288u)
                                : (l == 0u ? 0u : (l == 1u ? 4920u : 40864u));

    // Hash-path per-axis terms (uint32 wraparound, PRIMES = {1, P2, P3})
    const unsigned hy0 = y0 * P2;
    const unsigned hz0 = z0 * P3;
    const unsigned hxs[2] = { x0, x0 + 1u };
    const unsigned hys[2] = { hy0, hy0 + P2 };
    const unsigned hzs[2] = { hz0, hz0 + P3 };

    // Dense-path per-axis terms (sum < hm proven at compile time, no modulo)
    const unsigned side2 = side * side;
    const unsigned dys[2] = { y0 * side,  y0 * side + side };
    const unsigned dzs[2] = { z0 * side2, z0 * side2 + side2 };

    // Compute all 8 global indices first, then issue all 8 gathers for MLP.
    unsigned gidx[8];
#pragma unroll
    for (int c = 0; c < 8; ++c) {
        const int cx = c & 1, cy = (c >> 1) & 1, cz = (c >> 2) & 1;
        unsigned idx;
        if (hashed) {
            idx = (hxs[cx] ^ hys[cy] ^ hzs[cz]) & (HASH_SPLIT - 1u);
        } else {
            idx = hxs[cx] + dys[cy] + dzs[cz];
        }
        gidx[c] = off + idx;
    }

    float2 v[8];
#pragma unroll
    for (int c = 0; c < 8; ++c) {
        const unsigned g = gidx[c];
        const float2* q = (g < HASH_SPLIT) ? (ext + g) : (own + (g - HASH_SPLIT));
        v[c] = __ldg(q);
    }

    // Trilinear weights: corner bit d=0 -> x, bit 1 -> y, bit 2 -> z.
    const float wx[2] = { 1.0f - fx, fx };
    const float wy[2] = { 1.0f - fy, fy };
    const float wz[2] = { 1.0f - fz, fz };

    float accx = 0.0f, accy = 0.0f;
#pragma unroll
    for (int c = 0; c < 8; ++c) {
        const int cx = c & 1, cy = (c >> 1) & 1, cz = (c >> 2) & 1;
        const float w = wx[cx] * wy[cy] * wz[cz];
        accx += w * v[c].x;
        accy += w * v[c].y;
    }

    // out[b, l*2 + {0,1}] as one float2 store: out2[b*16 + l] == out2[gtid].
    out[gtid] = make_float2(accx, accy);
}

extern "C" void kernel_launch(void* const* d_in, const int* in_sizes, int n_in,
                              void* d_out, int out_size)
{
    const float*  pts = (const float*)d_in[0];        // [B, 3]
    const float2* ext = (const float2*)d_in[1];       // [524288, 2]
    const float2* own = (const float2*)d_in[2];       // [N_TABLE - 524288, 2]
    float2* out = (float2*)d_out;                     // [B, 32] floats = [B*16] float2

    // B * L threads = 1048576 * 16 = 16777216; 65536 blocks x 256 threads.
    grid_encode_kernel<<<65536, 256>>>(pts, ext, own, out);
}

// round 2
// speedup vs baseline: 1.1251x; 1.1251x over previous
#include <cuda_runtime.h>
#include <stdint.h>

// Compile-time constants for this problem instance:
//   B = 1048576, D = 3, L = 16, C = 2, H = 16, S = 1.0
//   res(l) = 16 << l, side(l) = res+1
//   dense levels: l = 0,1,2 ; hashed levels: l >= 3, hm = 2^19
//   offsets: 0, 4920, 40864, 315496, then +524288 per level
//   table = concat(ext[524288,2], own[.,2])
//
// R2: corner-pair vectorization. The x-corner pair (x0,x0+1) maps to
// consecutive table indices {2m,2m+1} whenever (ia^ib)==1 (always testable),
// which happens for all dense pairs with even ia and all hashed pairs with
// even x0 (PRIMES[0]==1 => h(x0)^h(x0+1)==1). Such pairs are fetched with one
// 16B-aligned LDG.128 (one L1 wavefront, one 32B sector) instead of two
// LDG.64s. Expected ~25% reduction in L1 wavefronts / L2 sectors.

#define HASH_SPLIT 524288u
#define P2 2654435761u
#define P3 805459861u

__device__ __forceinline__ const float2* tptr(unsigned g,
                                              const float2* __restrict__ ext,
                                              const float2* __restrict__ own)
{
    return (g < HASH_SPLIT) ? (ext + g) : (own + (g - HASH_SPLIT));
}

__global__ void __launch_bounds__(256)
grid_encode_kernel(const float* __restrict__ pts,
                   const float2* __restrict__ ext,
                   const float2* __restrict__ own,
                   float2* __restrict__ out)
{
    const unsigned gtid = blockIdx.x * 256u + threadIdx.x;
    const unsigned b = gtid >> 4;
    const unsigned l = gtid & 15u;

    const float px_in = __ldg(&pts[3u * b + 0u]);
    const float py_in = __ldg(&pts[3u * b + 1u]);
    const float pz_in = __ldg(&pts[3u * b + 2u]);

    const unsigned res  = 16u << l;
    const float scale   = (float)(res - 1u);
    const unsigned side = res + 1u;

    const float posx = (px_in + 1.0f) * 0.5f * scale + 0.5f;
    const float posy = (py_in + 1.0f) * 0.5f * scale + 0.5f;
    const float posz = (pz_in + 1.0f) * 0.5f * scale + 0.5f;

    const float flx = floorf(posx);
    const float fly = floorf(posy);
    const float flz = floorf(posz);
    const float fx = posx - flx;
    const float fy = posy - fly;
    const float fz = posz - flz;
    const unsigned x0 = (unsigned)flx;
    const unsigned y0 = (unsigned)fly;
    const unsigned z0 = (unsigned)flz;

    const bool hashed = (l >= 3u);
    const unsigned off = hashed ? (315496u + (l - 3u) * 524288u)
                                : (l == 0u ? 0u : (l == 1u ? 4920u : 40864u));

    // Hash per-axis terms (uint32 wraparound; PRIMES = {1, P2, P3})
    const unsigned hy0 = y0 * P2;
    const unsigned hz0 = z0 * P3;
    const unsigned hys[2] = { hy0, hy0 + P2 };
    const unsigned hzs[2] = { hz0, hz0 + P3 };

    // Dense per-axis terms (no modulo needed: side^3 <= hm for l<=2)
    const unsigned side2 = side * side;
    const unsigned dys[2] = { y0 * side,  y0 * side + side };
    const unsigned dzs[2] = { z0 * side2, z0 * side2 + side2 };

    // Compute the 4 (y,z) corner-pair index pairs: [pair][x-bit]
    unsigned ia[4], ib[4];
#pragma unroll
    for (int p = 0; p < 4; ++p) {
        const int cy = p & 1, cz = (p >> 1) & 1;
        unsigned a, bdx;
        if (hashed) {
            const unsigned base = hys[cy] ^ hzs[cz];
            a   = ((x0 ^ base) & (HASH_SPLIT - 1u));
            bdx = (((x0 + 1u) ^ base) & (HASH_SPLIT - 1u));
        } else {
            const unsigned base = dys[cy] + dzs[cz];
            a   = x0 + base;
            bdx = a + 1u;
        }
        ia[p] = off + a;
        ib[p] = off + bdx;
    }

    // Fetch: one LDG.128 when the pair occupies one aligned 16B slot,
    // else two LDG.64. v[p][0] = x-corner 0, v[p][1] = x-corner 1.
    float2 v0[4], v1[4];
#pragma unroll
    for (int p = 0; p < 4; ++p) {
        const unsigned a = ia[p], bb = ib[p];
        if ((a ^ bb) == 1u) {
            const unsigned lo = a & ~1u;
            const float4 w4 = __ldg((const float4*)tptr(lo, ext, own));
            const bool swap = (a & 1u);
            v0[p] = swap ? make_float2(w4.z, w4.w) : make_float2(w4.x, w4.y);
            v1[p] = swap ? make_float2(w4.x, w4.y) : make_float2(w4.z, w4.w);
        } else {
            v0[p] = __ldg(tptr(a,  ext, own));
            v1[p] = __ldg(tptr(bb, ext, own));
        }
    }

    // Trilinear weights: pair p = (cy, cz); within pair, x-bit.
    const float wx0 = 1.0f - fx, wx1 = fx;
    const float wy[2] = { 1.0f - fy, fy };
    const float wz[2] = { 1.0f - fz, fz };

    float accx = 0.0f, accy = 0.0f;
#pragma unroll
    for (int p = 0; p < 4; ++p) {
        const int cy = p & 1, cz = (p >> 1) & 1;
        const float wyz = wy[cy] * wz[cz];
        accx += wyz * (wx0 * v0[p].x + wx1 * v1[p].x);
        accy += wyz * (wx0 * v0[p].y + wx1 * v1[p].y);
    }

    out[gtid] = make_float2(accx, accy);
}

extern "C" void kernel_launch(void* const* d_in, const int* in_sizes, int n_in,
                              void* d_out, int out_size)
{
    const float*  pts = (const float*)d_in[0];        // [B, 3]
    const float2* ext = (const float2*)d_in[1];       // [524288, 2]
    const float2* own = (const float2*)d_in[2];       // [N_TABLE - 524288, 2]
    float2* out = (float2*)d_out;                     // [B*16] float2

    grid_encode_kernel<<<65536, 256>>>(pts, ext, own, out);
}